// round 1
// baseline (speedup 1.0000x reference)
#include <cuda_runtime.h>
#include <math.h>

#define NN 100000
#define NE 800000
#define NG 2048

// ---------------- scratch (device globals; no runtime allocation) ----------------
__device__ float g_h[NN*64];
__device__ float g_h2[NN*64];
__device__ float g_agg[NN*320];        // per-node, 5 relations x 64 dims
__device__ float g_Wc[384*64];         // rows 0..319: W_r (basis-combined); 320..383: root
__device__ float g_invcnt[NN];
__device__ float g_e[NN];
__device__ int   g_gstart[NG+1];
__device__ float g_Wl[192*256];        // LSTM combined weight [k][gate]
__device__ float g_bl[256];
__device__ float g_qstar[NG*128];
__device__ float g_hx[NG*64];
__device__ float g_cx[NG*64];
__device__ float g_gates[NG*256];
__device__ float g_gmax[NG];
__device__ float g_out1[NG*64];

// ---------------- prep kernels ----------------
__global__ void k_wc(const float* __restrict__ att, const float* __restrict__ basis,
                     const float* __restrict__ root){
  int k = blockIdx.x, e = threadIdx.x;
  float s;
  if (k < 320){
    int r = k >> 6, d = k & 63;
    s = 0.f;
    #pragma unroll
    for (int b = 0; b < 5; b++) s += att[r*5+b] * basis[(b*64+d)*64+e];
  } else {
    s = root[(k-320)*64 + e];
  }
  g_Wc[k*64+e] = s;
}

__global__ void k_h0(const float* __restrict__ x, const float* __restrict__ w,
                     const float* __restrict__ b){
  int n = blockIdx.x, e = threadIdx.x;
  __shared__ float sx[15];
  if (e < 15) sx[e] = x[n*15+e];
  __syncthreads();
  float s = b[e];
  #pragma unroll
  for (int i = 0; i < 15; i++) s += sx[i]*w[i*64+e];
  g_h[n*64+e] = fmaxf(s, 0.f);
}

__global__ void k_count(const int* __restrict__ dst){
  int e = blockIdx.x*blockDim.x + threadIdx.x;
  if (e < NE) atomicAdd(&g_invcnt[dst[e]], 1.0f);
}

__global__ void k_inv(){
  int n = blockIdx.x*blockDim.x + threadIdx.x;
  if (n < NN) g_invcnt[n] = 1.0f / fmaxf(g_invcnt[n], 1.0f);
}

__global__ void k_gstart(const int* __restrict__ batch){
  int g = blockIdx.x*blockDim.x + threadIdx.x;
  if (g > NG) return;
  int lo = 0, hi = NN;
  while (lo < hi){ int mid = (lo+hi) >> 1; if (batch[mid] < g) lo = mid+1; else hi = mid; }
  g_gstart[g] = lo;
}

__global__ void k_wl(const float* __restrict__ w_ih, const float* __restrict__ w_hh,
                     const float* __restrict__ b_ih, const float* __restrict__ b_hh){
  int k = blockIdx.x, j = threadIdx.x;
  g_Wl[k*256+j] = (k < 128) ? w_ih[j*128+k] : w_hh[j*64 + (k-128)];
  if (k == 0) g_bl[j] = b_ih[j] + b_hh[j];
}

// ---------------- RGCN propagation ----------------
// scatter h[src] into relation-separated accumulators (vector reduction atomics)
__global__ void k_edge(const float* __restrict__ hin, const int* __restrict__ ei,
                       const int* __restrict__ et){
  int t = blockIdx.x*blockDim.x + threadIdx.x;
  int e = t >> 4;
  if (e >= NE) return;
  int p = t & 15;
  int src = ei[e];
  int dst = ei[NE + e];
  int rel = et[e];
  float4 v = *(const float4*)(hin + src*64 + p*4);
  float* a = g_agg + (dst*320 + rel*64 + p*4);
  asm volatile("red.global.add.v4.f32 [%0], {%1,%2,%3,%4};"
               :: "l"(a), "f"(v.x), "f"(v.y), "f"(v.z), "f"(v.w) : "memory");
}

// h_out = relu( [agg*invcnt | h_in] @ Wc + conv_b ), tiled GEMM M=100000, K=384, N=64
__global__ void __launch_bounds__(256) k_node(const float* __restrict__ hin,
                                              float* __restrict__ hout,
                                              const float* __restrict__ cb){
  __shared__ float As[64][36];
  __shared__ float Bs[32][64];
  int tid = threadIdx.x;
  int tx = tid & 15, ty = tid >> 4;
  int m0 = blockIdx.x * 64;
  int lrow = tid >> 2;
  int lk = (tid & 3) * 8;
  int grow = m0 + lrow;
  bool rok = grow < NN;
  float ic = rok ? g_invcnt[grow] : 0.f;
  int bk = tid >> 3, be = (tid & 7) * 8;
  float acc[4][4] = {};
  for (int kk = 0; kk < 12; kk++){
    float4 a0 = {0,0,0,0}, a1 = {0,0,0,0};
    if (rok){
      if (kk < 10){
        const float* p = g_agg + grow*320 + kk*32 + lk;
        a0 = *(const float4*)p; a1 = *(const float4*)(p+4);
        a0.x*=ic; a0.y*=ic; a0.z*=ic; a0.w*=ic;
        a1.x*=ic; a1.y*=ic; a1.z*=ic; a1.w*=ic;
      } else {
        const float* p = hin + grow*64 + (kk-10)*32 + lk;
        a0 = *(const float4*)p; a1 = *(const float4*)(p+4);
      }
    }
    const float* wp = g_Wc + (kk*32 + bk)*64 + be;
    float4 b0 = *(const float4*)wp;
    float4 b1 = *(const float4*)(wp+4);
    __syncthreads();
    *(float4*)&As[lrow][lk]   = a0;
    *(float4*)&As[lrow][lk+4] = a1;
    *(float4*)&Bs[bk][be]     = b0;
    *(float4*)&Bs[bk][be+4]   = b1;
    __syncthreads();
    #pragma unroll
    for (int k = 0; k < 32; k++){
      float4 bv = *(float4*)&Bs[k][tx*4];
      #pragma unroll
      for (int i = 0; i < 4; i++){
        float av = As[ty*4+i][k];
        acc[i][0] += av*bv.x;
        acc[i][1] += av*bv.y;
        acc[i][2] += av*bv.z;
        acc[i][3] += av*bv.w;
      }
    }
  }
  #pragma unroll
  for (int i = 0; i < 4; i++){
    int m = m0 + ty*4 + i;
    if (m < NN){
      float4 o;
      o.x = fmaxf(acc[i][0] + cb[tx*4+0], 0.f);
      o.y = fmaxf(acc[i][1] + cb[tx*4+1], 0.f);
      o.z = fmaxf(acc[i][2] + cb[tx*4+2], 0.f);
      o.w = fmaxf(acc[i][3] + cb[tx*4+3], 0.f);
      *(float4*)(hout + m*64 + tx*4) = o;
    }
  }
}

// ---------------- Set2Set ----------------
// gates = [q_star | hx] @ Wl + bl, GEMM M=2048, K=192, N=256
__global__ void __launch_bounds__(256) k_gates(){
  __shared__ float As[64][36];
  __shared__ float Bs[32][64];
  int tid = threadIdx.x;
  int tx = tid & 15, ty = tid >> 4;
  int m0 = blockIdx.x * 64;
  int n0 = blockIdx.y * 64;
  int lrow = tid >> 2;
  int lk = (tid & 3) * 8;
  int grow = m0 + lrow;
  int bk = tid >> 3, be = (tid & 7) * 8;
  float acc[4][4] = {};
  for (int kk = 0; kk < 6; kk++){
    int kb = kk * 32;
    float4 a0, a1;
    if (kk < 4){
      const float* p = g_qstar + grow*128 + kb + lk;
      a0 = *(const float4*)p; a1 = *(const float4*)(p+4);
    } else {
      const float* p = g_hx + grow*64 + (kb - 128) + lk;
      a0 = *(const float4*)p; a1 = *(const float4*)(p+4);
    }
    const float* wp = g_Wl + (kb + bk)*256 + n0 + be;
    float4 b0 = *(const float4*)wp;
    float4 b1 = *(const float4*)(wp+4);
    __syncthreads();
    *(float4*)&As[lrow][lk]   = a0;
    *(float4*)&As[lrow][lk+4] = a1;
    *(float4*)&Bs[bk][be]     = b0;
    *(float4*)&Bs[bk][be+4]   = b1;
    __syncthreads();
    #pragma unroll
    for (int k = 0; k < 32; k++){
      float4 bv = *(float4*)&Bs[k][tx*4];
      #pragma unroll
      for (int i = 0; i < 4; i++){
        float av = As[ty*4+i][k];
        acc[i][0] += av*bv.x;
        acc[i][1] += av*bv.y;
        acc[i][2] += av*bv.z;
        acc[i][3] += av*bv.w;
      }
    }
  }
  #pragma unroll
  for (int i = 0; i < 4; i++){
    int m = m0 + ty*4 + i;
    float* op = g_gates + m*256 + n0 + tx*4;
    op[0] = acc[i][0] + g_bl[n0 + tx*4 + 0];
    op[1] = acc[i][1] + g_bl[n0 + tx*4 + 1];
    op[2] = acc[i][2] + g_bl[n0 + tx*4 + 2];
    op[3] = acc[i][3] + g_bl[n0 + tx*4 + 3];
  }
}

__device__ __forceinline__ float sigf(float v){ return 1.0f/(1.0f + expf(-v)); }

__global__ void k_update(){
  int t = blockIdx.x*blockDim.x + threadIdx.x;
  if (t >= NG*64) return;
  int g = t >> 6, d = t & 63;
  const float* ga = g_gates + g*256;
  float iv = sigf(ga[d]);
  float fv = sigf(ga[64+d]);
  float gv = tanhf(ga[128+d]);
  float ov = sigf(ga[192+d]);
  float c = fv * g_cx[t] + iv * gv;
  float h = ov * tanhf(c);
  g_cx[t] = c;
  g_hx[t] = h;
}

__global__ void k_e(const float* __restrict__ h, const int* __restrict__ batch){
  int gt = blockIdx.x*blockDim.x + threadIdx.x;
  int n = gt >> 5;
  if (n >= NN) return;
  int l = gt & 31;
  int b = batch[n];
  const float* hp = h + n*64;
  const float* qp = g_hx + b*64;
  float s = hp[l]*qp[l] + hp[l+32]*qp[l+32];
  #pragma unroll
  for (int o = 16; o; o >>= 1) s += __shfl_xor_sync(0xffffffffu, s, o);
  if (l == 0) g_e[n] = s;
}

__global__ void k_segmax(){
  int gt = blockIdx.x*blockDim.x + threadIdx.x;
  int g = gt >> 5;
  if (g >= NG) return;
  int l = gt & 31;
  int s0 = g_gstart[g], s1 = g_gstart[g+1];
  float m = -3.0e38f;
  for (int i = s0 + l; i < s1; i += 32) m = fmaxf(m, g_e[i]);
  #pragma unroll
  for (int o = 16; o; o >>= 1) m = fmaxf(m, __shfl_xor_sync(0xffffffffu, m, o));
  if (l == 0) g_gmax[g] = m;
}

__global__ void k_weighted(const float* __restrict__ h){
  int g = blockIdx.x, d = threadIdx.x;
  int s0 = g_gstart[g], s1 = g_gstart[g+1];
  float m = g_gmax[g];
  float s = 0.f, r = 0.f;
  #pragma unroll 4
  for (int i = s0; i < s1; i++){
    float a = expf(g_e[i] - m);
    s += a;
    r += a * h[i*64 + d];
  }
  g_qstar[g*128 + d]      = g_hx[g*64 + d];
  g_qstar[g*128 + 64 + d] = (s > 0.f) ? (r / s) : 0.f;
}

// ---------------- head ----------------
__global__ void k_lin1(const float* __restrict__ w, const float* __restrict__ b){
  int t = blockIdx.x*blockDim.x + threadIdx.x;
  if (t >= NG*64) return;
  int g = t >> 6, e = t & 63;
  float s = b[e];
  const float* q = g_qstar + g*128;
  #pragma unroll 8
  for (int k = 0; k < 128; k++) s += q[k]*w[k*64+e];
  g_out1[t] = fmaxf(s, 0.f);
}

__global__ void k_lin2(const float* __restrict__ w, const float* __restrict__ b,
                       float* __restrict__ out){
  int t = blockIdx.x*blockDim.x + threadIdx.x;
  if (t >= NG*12) return;
  int g = t / 12, j = t % 12;
  float s = b[j];
  const float* o1 = g_out1 + g*64;
  #pragma unroll 8
  for (int d = 0; d < 64; d++) s += o1[d]*w[d*12+j];
  out[t] = s;
}

// ---------------- launch ----------------
extern "C" void kernel_launch(void* const* d_in, const int* in_sizes, int n_in,
                              void* d_out, int out_size){
  const float* x      = (const float*)d_in[0];
  const int*   ei     = (const int*)  d_in[1];
  const int*   et     = (const int*)  d_in[2];
  const int*   batch  = (const int*)  d_in[3];
  const float* lin0_w = (const float*)d_in[4];
  const float* lin0_b = (const float*)d_in[5];
  const float* basis  = (const float*)d_in[6];
  const float* att    = (const float*)d_in[7];
  const float* root   = (const float*)d_in[8];
  const float* conv_b = (const float*)d_in[9];
  const float* w_ih   = (const float*)d_in[10];
  const float* w_hh   = (const float*)d_in[11];
  const float* b_ih   = (const float*)d_in[12];
  const float* b_hh   = (const float*)d_in[13];
  const float* lin1_w = (const float*)d_in[14];
  const float* lin1_b = (const float*)d_in[15];
  const float* lin2_w = (const float*)d_in[16];
  const float* lin2_b = (const float*)d_in[17];
  float* out = (float*)d_out;

  void *p_agg=0, *p_inv=0, *p_qs=0, *p_hx=0, *p_cx=0, *p_h=0, *p_h2=0;
  cudaGetSymbolAddress(&p_agg, g_agg);
  cudaGetSymbolAddress(&p_inv, g_invcnt);
  cudaGetSymbolAddress(&p_qs,  g_qstar);
  cudaGetSymbolAddress(&p_hx,  g_hx);
  cudaGetSymbolAddress(&p_cx,  g_cx);
  cudaGetSymbolAddress(&p_h,   g_h);
  cudaGetSymbolAddress(&p_h2,  g_h2);

  k_wc<<<384, 64>>>(att, basis, root);
  k_h0<<<NN, 64>>>(x, lin0_w, lin0_b);
  cudaMemsetAsync(p_inv, 0, NN*sizeof(float));
  k_count<<<(NE+255)/256, 256>>>(ei + NE);
  k_inv<<<(NN+255)/256, 256>>>();
  k_gstart<<<(NG+256)/256, 256>>>(batch);
  k_wl<<<192, 256>>>(w_ih, w_hh, b_ih, b_hh);
  cudaMemsetAsync(p_qs, 0, NG*128*sizeof(float));
  cudaMemsetAsync(p_hx, 0, NG*64*sizeof(float));
  cudaMemsetAsync(p_cx, 0, NG*64*sizeof(float));

  float* hA = (float*)p_h;
  float* hB = (float*)p_h2;
  for (int s = 0; s < 6; s++){
    cudaMemsetAsync(p_agg, 0, (size_t)NN*320*sizeof(float));
    k_edge<<<(NE*16)/256, 256>>>(hA, ei, et);
    k_node<<<(NN+63)/64, 256>>>(hA, hB, conv_b);
    float* tmp = hA; hA = hB; hB = tmp;
  }

  for (int t = 0; t < 6; t++){
    k_gates<<<dim3(NG/64, 4), 256>>>();
    k_update<<<(NG*64+255)/256, 256>>>();
    k_e<<<(NN*32+255)/256, 256>>>(hA, batch);
    k_segmax<<<(NG*32+255)/256, 256>>>();
    k_weighted<<<NG, 64>>>(hA);
  }

  k_lin1<<<(NG*64+255)/256, 256>>>(lin1_w, lin1_b);
  k_lin2<<<(NG*12+255)/256, 256>>>(lin2_w, lin2_b, out);
}